// round 1
// baseline (speedup 1.0000x reference)
#include <cuda_runtime.h>

// Problem dims (fixed)
#define NB   8
#define LQ   1024
#define SSEQ 4096
#define DD   512

// ---------------- static device scratch (no allocations allowed) ----------------
static __device__ float g_q  [NB * LQ * DD];          //  16.8 MB
static __device__ float g_k  [NB * SSEQ * DD];        //  67 MB
static __device__ float g_v  [NB * SSEQ * DD];        //  67 MB
static __device__ float g_q2 [NB * LQ];
static __device__ float g_k2 [NB * SSEQ];
static __device__ float g_s  [NB * LQ * SSEQ];        // 134 MB (scores -> attn in place)
static __device__ float g_msg[NB * LQ * DD];
static __device__ float g_mw [NB * LQ * DD];
static __device__ float g_mln[NB * LQ * DD];
static __device__ float g_hid[NB * LQ * 2 * DD];      //  33.5 MB
static __device__ float g_ffn[NB * LQ * DD];

// ---------------- reductions ----------------
__device__ __forceinline__ float warpReduceSum(float v) {
    v += __shfl_xor_sync(0xffffffffu, v, 16);
    v += __shfl_xor_sync(0xffffffffu, v, 8);
    v += __shfl_xor_sync(0xffffffffu, v, 4);
    v += __shfl_xor_sync(0xffffffffu, v, 2);
    v += __shfl_xor_sync(0xffffffffu, v, 1);
    return v;
}
__device__ __forceinline__ float warpReduceMax(float v) {
    v = fmaxf(v, __shfl_xor_sync(0xffffffffu, v, 16));
    v = fmaxf(v, __shfl_xor_sync(0xffffffffu, v, 8));
    v = fmaxf(v, __shfl_xor_sync(0xffffffffu, v, 4));
    v = fmaxf(v, __shfl_xor_sync(0xffffffffu, v, 2));
    v = fmaxf(v, __shfl_xor_sync(0xffffffffu, v, 1));
    return v;
}
__device__ __forceinline__ float blockAllReduceSum(float v, float* sh) {
    int lane = threadIdx.x & 31, wid = threadIdx.x >> 5;
    v = warpReduceSum(v);
    if (lane == 0) sh[wid] = v;
    __syncthreads();
    int nw = blockDim.x >> 5;
    float t = (lane < nw) ? sh[lane] : 0.0f;
    t = warpReduceSum(t);
    __syncthreads();
    return t;
}
__device__ __forceinline__ float blockAllReduceMax(float v, float* sh) {
    int lane = threadIdx.x & 31, wid = threadIdx.x >> 5;
    v = warpReduceMax(v);
    if (lane == 0) sh[wid] = v;
    __syncthreads();
    int nw = blockDim.x >> 5;
    float t = (lane < nw) ? sh[lane] : -3.0e38f;
    t = warpReduceMax(t);
    __syncthreads();
    return t;
}

// ======================================================================
// SGEMM NN (batched): C[M,N] = A[M,K] * B[K,N]. 128x128x8 tile, 256 thr,
// 8x8 microtile per thread (split 64+64 pattern, conflict-free LDS.128).
// All dims multiples of 128 (M,N) and 8 (K) -> no bounds checks.
// ======================================================================
__global__ __launch_bounds__(256)
void sgemm_nn(const float* __restrict__ gA, const float* __restrict__ gB,
              float* __restrict__ gC, int N, int K,
              long long sA, long long sB, long long sC)
{
    __shared__ __align__(16) float As[8][132];
    __shared__ __align__(16) float Bs[8][132];

    const float* A = gA + blockIdx.z * sA + (long long)blockIdx.y * 128 * K;
    const float* B = gB + blockIdx.z * sB + blockIdx.x * 128;
    float*       C = gC + blockIdx.z * sC + (long long)blockIdx.y * 128 * N + blockIdx.x * 128;

    int tid = threadIdx.x;
    int tx = tid & 15, ty = tid >> 4;
    int arow = tid >> 1,  acol = (tid & 1) * 4;
    int brow = tid >> 5,  bcol = (tid & 31) * 4;

    float4 aReg = *(const float4*)(A + (long long)arow * K + acol);
    float4 bReg = *(const float4*)(B + (long long)brow * N + bcol);

    float acc[8][8];
#pragma unroll
    for (int i = 0; i < 8; i++)
#pragma unroll
        for (int j = 0; j < 8; j++) acc[i][j] = 0.0f;

    for (int k0 = 0; k0 < K; k0 += 8) {
        As[acol + 0][arow] = aReg.x;
        As[acol + 1][arow] = aReg.y;
        As[acol + 2][arow] = aReg.z;
        As[acol + 3][arow] = aReg.w;
        *(float4*)&Bs[brow][bcol] = bReg;
        __syncthreads();
        if (k0 + 8 < K) {
            aReg = *(const float4*)(A + (long long)arow * K + (k0 + 8) + acol);
            bReg = *(const float4*)(B + (long long)(k0 + 8 + brow) * N + bcol);
        }
#pragma unroll
        for (int kk = 0; kk < 8; kk++) {
            float4 a0 = *(const float4*)&As[kk][ty * 4];
            float4 a1 = *(const float4*)&As[kk][64 + ty * 4];
            float4 b0 = *(const float4*)&Bs[kk][tx * 4];
            float4 b1 = *(const float4*)&Bs[kk][64 + tx * 4];
            float av[8] = {a0.x, a0.y, a0.z, a0.w, a1.x, a1.y, a1.z, a1.w};
            float bv[8] = {b0.x, b0.y, b0.z, b0.w, b1.x, b1.y, b1.z, b1.w};
#pragma unroll
            for (int i = 0; i < 8; i++)
#pragma unroll
                for (int j = 0; j < 8; j++)
                    acc[i][j] = fmaf(av[i], bv[j], acc[i][j]);
        }
        __syncthreads();
    }
#pragma unroll
    for (int i = 0; i < 8; i++) {
        int r = (i < 4) ? (ty * 4 + i) : (64 + ty * 4 + i - 4);
        float4 c0 = make_float4(acc[i][0], acc[i][1], acc[i][2], acc[i][3]);
        float4 c1 = make_float4(acc[i][4], acc[i][5], acc[i][6], acc[i][7]);
        *(float4*)(C + (long long)r * N + tx * 4)      = c0;
        *(float4*)(C + (long long)r * N + 64 + tx * 4) = c1;
    }
}

// ======================================================================
// SGEMM NT with distance epilogue (batched):
// scores[m,n] = sqrt(max(q2[m] + k2[n] - 2 * (A[m,:] . B[n,:]), 0))
// A = q [LQ, DD], B = k [SSEQ, DD], both row-major; K = DD.
// ======================================================================
__global__ __launch_bounds__(256)
void sgemm_nt_dist(const float* __restrict__ gA, const float* __restrict__ gB,
                   float* __restrict__ gC, int N, int K,
                   long long sA, long long sB, long long sC)
{
    __shared__ __align__(16) float As[8][132];
    __shared__ __align__(16) float Bs[8][132];

    const float* A = gA + blockIdx.z * sA + (long long)blockIdx.y * 128 * K;
    const float* B = gB + blockIdx.z * sB + (long long)blockIdx.x * 128 * K;
    float*       C = gC + blockIdx.z * sC + (long long)blockIdx.y * 128 * N + blockIdx.x * 128;

    int tid = threadIdx.x;
    int tx = tid & 15, ty = tid >> 4;
    int arow = tid >> 1, acol = (tid & 1) * 4;   // same pattern for both operands

    float4 aReg = *(const float4*)(A + (long long)arow * K + acol);
    float4 bReg = *(const float4*)(B + (long long)arow * K + acol);

    float acc[8][8];
#pragma unroll
    for (int i = 0; i < 8; i++)
#pragma unroll
        for (int j = 0; j < 8; j++) acc[i][j] = 0.0f;

    for (int k0 = 0; k0 < K; k0 += 8) {
        As[acol + 0][arow] = aReg.x;
        As[acol + 1][arow] = aReg.y;
        As[acol + 2][arow] = aReg.z;
        As[acol + 3][arow] = aReg.w;
        Bs[acol + 0][arow] = bReg.x;
        Bs[acol + 1][arow] = bReg.y;
        Bs[acol + 2][arow] = bReg.z;
        Bs[acol + 3][arow] = bReg.w;
        __syncthreads();
        if (k0 + 8 < K) {
            aReg = *(const float4*)(A + (long long)arow * K + (k0 + 8) + acol);
            bReg = *(const float4*)(B + (long long)arow * K + (k0 + 8) + acol);
        }
#pragma unroll
        for (int kk = 0; kk < 8; kk++) {
            float4 a0 = *(const float4*)&As[kk][ty * 4];
            float4 a1 = *(const float4*)&As[kk][64 + ty * 4];
            float4 b0 = *(const float4*)&Bs[kk][tx * 4];
            float4 b1 = *(const float4*)&Bs[kk][64 + tx * 4];
            float av[8] = {a0.x, a0.y, a0.z, a0.w, a1.x, a1.y, a1.z, a1.w};
            float bv[8] = {b0.x, b0.y, b0.z, b0.w, b1.x, b1.y, b1.z, b1.w};
#pragma unroll
            for (int i = 0; i < 8; i++)
#pragma unroll
                for (int j = 0; j < 8; j++)
                    acc[i][j] = fmaf(av[i], bv[j], acc[i][j]);
        }
        __syncthreads();
    }

    const float* q2p = g_q2 + blockIdx.z * LQ   + blockIdx.y * 128;
    const float* k2p = g_k2 + blockIdx.z * SSEQ + blockIdx.x * 128;

#pragma unroll
    for (int i = 0; i < 8; i++) {
        int r = (i < 4) ? (ty * 4 + i) : (64 + ty * 4 + i - 4);
        float qq = q2p[r];
#pragma unroll
        for (int j = 0; j < 8; j++) {
            int c = (j < 4) ? (tx * 4 + j) : (64 + tx * 4 + j - 4);
            float d = qq + k2p[c] - 2.0f * acc[i][j];
            acc[i][j] = sqrtf(fmaxf(d, 0.0f));
        }
        float4 c0 = make_float4(acc[i][0], acc[i][1], acc[i][2], acc[i][3]);
        float4 c1 = make_float4(acc[i][4], acc[i][5], acc[i][6], acc[i][7]);
        *(float4*)(C + (long long)r * N + tx * 4)      = c0;
        *(float4*)(C + (long long)r * N + 64 + tx * 4) = c1;
    }
}

// ======================================================================
// Dual-A SGEMM + ReLU:  hid = relu( x @ W1[0:512,:] + mln @ W1[512:1024,:] )
// M = 8192, N = 1024, K = 1024 (512 from each A). lda = 512, ldb = 1024.
// ======================================================================
__global__ __launch_bounds__(256)
void sgemm_dual_relu(const float* __restrict__ gA1, const float* __restrict__ gA2,
                     const float* __restrict__ gB, float* __restrict__ gC)
{
    const int N = 2 * DD;   // 1024
    const int K = 2 * DD;   // 1024 total
    __shared__ __align__(16) float As[8][132];
    __shared__ __align__(16) float Bs[8][132];

    const float* A1 = gA1 + (long long)blockIdx.y * 128 * DD;
    const float* A2 = gA2 + (long long)blockIdx.y * 128 * DD;
    const float* B  = gB + blockIdx.x * 128;
    float*       C  = gC + (long long)blockIdx.y * 128 * N + blockIdx.x * 128;

    int tid = threadIdx.x;
    int tx = tid & 15, ty = tid >> 4;
    int arow = tid >> 1, acol = (tid & 1) * 4;
    int brow = tid >> 5, bcol = (tid & 31) * 4;

    float4 aReg = *(const float4*)(A1 + (long long)arow * DD + acol);
    float4 bReg = *(const float4*)(B + (long long)brow * N + bcol);

    float acc[8][8];
#pragma unroll
    for (int i = 0; i < 8; i++)
#pragma unroll
        for (int j = 0; j < 8; j++) acc[i][j] = 0.0f;

    for (int k0 = 0; k0 < K; k0 += 8) {
        As[acol + 0][arow] = aReg.x;
        As[acol + 1][arow] = aReg.y;
        As[acol + 2][arow] = aReg.z;
        As[acol + 3][arow] = aReg.w;
        *(float4*)&Bs[brow][bcol] = bReg;
        __syncthreads();
        if (k0 + 8 < K) {
            int kn = k0 + 8;
            const float* Ab = (kn < DD) ? (A1 + kn) : (A2 + (kn - DD));
            aReg = *(const float4*)(Ab + (long long)arow * DD + acol);
            bReg = *(const float4*)(B + (long long)(kn + brow) * N + bcol);
        }
#pragma unroll
        for (int kk = 0; kk < 8; kk++) {
            float4 a0 = *(const float4*)&As[kk][ty * 4];
            float4 a1 = *(const float4*)&As[kk][64 + ty * 4];
            float4 b0 = *(const float4*)&Bs[kk][tx * 4];
            float4 b1 = *(const float4*)&Bs[kk][64 + tx * 4];
            float av[8] = {a0.x, a0.y, a0.z, a0.w, a1.x, a1.y, a1.z, a1.w};
            float bv[8] = {b0.x, b0.y, b0.z, b0.w, b1.x, b1.y, b1.z, b1.w};
#pragma unroll
            for (int i = 0; i < 8; i++)
#pragma unroll
                for (int j = 0; j < 8; j++)
                    acc[i][j] = fmaf(av[i], bv[j], acc[i][j]);
        }
        __syncthreads();
    }
#pragma unroll
    for (int i = 0; i < 8; i++) {
        int r = (i < 4) ? (ty * 4 + i) : (64 + ty * 4 + i - 4);
        float4 c0 = make_float4(fmaxf(acc[i][0], 0.f), fmaxf(acc[i][1], 0.f),
                                fmaxf(acc[i][2], 0.f), fmaxf(acc[i][3], 0.f));
        float4 c1 = make_float4(fmaxf(acc[i][4], 0.f), fmaxf(acc[i][5], 0.f),
                                fmaxf(acc[i][6], 0.f), fmaxf(acc[i][7], 0.f));
        *(float4*)(C + (long long)r * N + tx * 4)      = c0;
        *(float4*)(C + (long long)r * N + 64 + tx * 4) = c1;
    }
}

// ---------------- row squared-norm: out[row] = sum(X[row,:]^2), D = 512 ----------------
__global__ __launch_bounds__(128)
void rownorm2_kernel(const float* __restrict__ X, float* __restrict__ out)
{
    __shared__ float sh[32];
    long long row = blockIdx.x;
    const float* x = X + row * DD;
    float4 v = *(const float4*)(x + threadIdx.x * 4);
    float s = v.x * v.x + v.y * v.y + v.z * v.z + v.w * v.w;
    s = blockAllReduceSum(s, sh);
    if (threadIdx.x == 0) out[row] = s;
}

// ---------------- softmax over S=4096, in place on g_s ----------------
__global__ __launch_bounds__(256)
void softmax_rows_kernel()
{
    __shared__ float sh[32];
    long long row = blockIdx.x;           // NB*LQ rows
    float* p = g_s + row * SSEQ;
    int t = threadIdx.x;

    float4 f[4];
    float mx = -3.0e38f;
#pragma unroll
    for (int i = 0; i < 4; i++) {
        f[i] = *(const float4*)(p + i * 1024 + t * 4);
        mx = fmaxf(mx, fmaxf(fmaxf(f[i].x, f[i].y), fmaxf(f[i].z, f[i].w)));
    }
    mx = blockAllReduceMax(mx, sh);

    float sum = 0.0f;
#pragma unroll
    for (int i = 0; i < 4; i++) {
        f[i].x = __expf(f[i].x - mx);
        f[i].y = __expf(f[i].y - mx);
        f[i].z = __expf(f[i].z - mx);
        f[i].w = __expf(f[i].w - mx);
        sum += f[i].x + f[i].y + f[i].z + f[i].w;
    }
    sum = blockAllReduceSum(sum, sh);
    float r = 1.0f / sum;
#pragma unroll
    for (int i = 0; i < 4; i++) {
        f[i].x *= r; f[i].y *= r; f[i].z *= r; f[i].w *= r;
        *(float4*)(p + i * 1024 + t * 4) = f[i];
    }
}

// ---------------- LayerNorm over D=512 (+ optional residual) ----------------
__global__ __launch_bounds__(128)
void layernorm_kernel(const float* __restrict__ X, const float* __restrict__ G,
                      const float* __restrict__ Bv, const float* __restrict__ R,
                      float* __restrict__ O)
{
    __shared__ float sh[32];
    long long row = blockIdx.x;
    int c = threadIdx.x * 4;
    float4 v = *(const float4*)(X + row * DD + c);

    float s = v.x + v.y + v.z + v.w;
    s = blockAllReduceSum(s, sh);
    float mu = s * (1.0f / DD);

    float d0 = v.x - mu, d1 = v.y - mu, d2 = v.z - mu, d3 = v.w - mu;
    float s2 = d0 * d0 + d1 * d1 + d2 * d2 + d3 * d3;
    s2 = blockAllReduceSum(s2, sh);
    float inv = rsqrtf(s2 * (1.0f / DD) + 1e-5f);

    float4 gg = *(const float4*)(G + c);
    float4 bb = *(const float4*)(Bv + c);
    float4 o;
    o.x = d0 * inv * gg.x + bb.x;
    o.y = d1 * inv * gg.y + bb.y;
    o.z = d2 * inv * gg.z + bb.z;
    o.w = d3 * inv * gg.w + bb.w;
    if (R) {
        float4 rr = *(const float4*)(R + row * DD + c);
        o.x += rr.x; o.y += rr.y; o.z += rr.z; o.w += rr.w;
    }
    *(float4*)(O + row * DD + c) = o;
}

// ======================================================================
extern "C" void kernel_launch(void* const* d_in, const int* in_sizes, int n_in,
                              void* d_out, int out_size)
{
    (void)in_sizes; (void)n_in; (void)out_size;
    const float* x   = (const float*)d_in[0];
    const float* src = (const float*)d_in[1];
    const float* Wq  = (const float*)d_in[2];
    const float* Wk  = (const float*)d_in[3];
    const float* Wv  = (const float*)d_in[4];
    const float* Wm  = (const float*)d_in[5];
    const float* W1  = (const float*)d_in[6];
    const float* W2  = (const float*)d_in[7];
    const float* g1  = (const float*)d_in[8];
    const float* b1  = (const float*)d_in[9];
    const float* g2  = (const float*)d_in[10];
    const float* b2  = (const float*)d_in[11];
    float* out = (float*)d_out;

    float *q, *k, *v, *q2, *k2, *sc, *msg, *mw, *mln, *hid, *ffn;
    cudaGetSymbolAddress((void**)&q,   g_q);
    cudaGetSymbolAddress((void**)&k,   g_k);
    cudaGetSymbolAddress((void**)&v,   g_v);
    cudaGetSymbolAddress((void**)&q2,  g_q2);
    cudaGetSymbolAddress((void**)&k2,  g_k2);
    cudaGetSymbolAddress((void**)&sc,  g_s);
    cudaGetSymbolAddress((void**)&msg, g_msg);
    cudaGetSymbolAddress((void**)&mw,  g_mw);
    cudaGetSymbolAddress((void**)&mln, g_mln);
    cudaGetSymbolAddress((void**)&hid, g_hid);
    cudaGetSymbolAddress((void**)&ffn, g_ffn);

    // 1. projections
    sgemm_nn<<<dim3(DD / 128, (NB * LQ) / 128, 1), 256>>>(x,   Wq, q, DD, DD, 0, 0, 0);
    sgemm_nn<<<dim3(DD / 128, (NB * SSEQ) / 128, 1), 256>>>(src, Wk, k, DD, DD, 0, 0, 0);
    sgemm_nn<<<dim3(DD / 128, (NB * SSEQ) / 128, 1), 256>>>(src, Wv, v, DD, DD, 0, 0, 0);

    // 2. squared row norms
    rownorm2_kernel<<<NB * LQ,   128>>>(q, q2);
    rownorm2_kernel<<<NB * SSEQ, 128>>>(k, k2);

    // 3. pairwise distances: sc = sqrt(max(q2 + k2 - 2 q.k, 0))   [batched NT gemm]
    sgemm_nt_dist<<<dim3(SSEQ / 128, LQ / 128, NB), 256>>>(
        q, k, sc, SSEQ, DD,
        (long long)LQ * DD, (long long)SSEQ * DD, (long long)LQ * SSEQ);

    // 4. softmax over S (in place)
    softmax_rows_kernel<<<NB * LQ, 256>>>();

    // 5. message = attn @ v   [batched NN gemm]
    sgemm_nn<<<dim3(DD / 128, LQ / 128, NB), 256>>>(
        sc, v, msg, DD, SSEQ,
        (long long)LQ * SSEQ, (long long)SSEQ * DD, (long long)LQ * DD);

    // 6. mw = message @ Wm ; mln = LN(mw, g1, b1)
    sgemm_nn<<<dim3(DD / 128, (NB * LQ) / 128, 1), 256>>>(msg, Wm, mw, DD, DD, 0, 0, 0);
    layernorm_kernel<<<NB * LQ, 128>>>(mw, g1, b1, nullptr, mln);

    // 7. hid = relu([x, mln] @ W1)
    sgemm_dual_relu<<<dim3((2 * DD) / 128, (NB * LQ) / 128, 1), 256>>>(x, mln, W1, hid);

    // 8. ffn = hid @ W2
    sgemm_nn<<<dim3(DD / 128, (NB * LQ) / 128, 1), 256>>>(hid, W2, ffn, DD, 2 * DD, 0, 0, 0);

    // 9. out = x + LN(ffn, g2, b2)
    layernorm_kernel<<<NB * LQ, 128>>>(ffn, g2, b2, x, out);
}

// round 2
// speedup vs baseline: 2.8526x; 2.8526x over previous
#include <cuda_runtime.h>

// Problem dims (fixed)
#define NB   8
#define LQ   1024
#define SSEQ 4096
#define DD   512

// ---------------- static device scratch (no allocations allowed) ----------------
static __device__ float g_q  [NB * LQ * DD];
static __device__ float g_k  [NB * SSEQ * DD];
static __device__ float g_v  [NB * SSEQ * DD];
static __device__ float g_q2 [NB * LQ];
static __device__ float g_k2 [NB * SSEQ];
static __device__ float g_s  [NB * LQ * SSEQ];        // scores -> attn in place
static __device__ float g_msg[NB * LQ * DD];
static __device__ float g_mw [NB * LQ * DD];
static __device__ float g_mln[NB * LQ * DD];
static __device__ float g_hid[NB * LQ * 2 * DD];
static __device__ float g_ffn[NB * LQ * DD];

__device__ __forceinline__ float to_tf32(float x) {
    float r;
    asm("cvt.rna.tf32.f32 %0, %1;" : "=f"(r) : "f"(x));
    return r;
}

// ---------------- reductions ----------------
__device__ __forceinline__ float warpReduceSum(float v) {
    v += __shfl_xor_sync(0xffffffffu, v, 16);
    v += __shfl_xor_sync(0xffffffffu, v, 8);
    v += __shfl_xor_sync(0xffffffffu, v, 4);
    v += __shfl_xor_sync(0xffffffffu, v, 2);
    v += __shfl_xor_sync(0xffffffffu, v, 1);
    return v;
}
__device__ __forceinline__ float warpReduceMax(float v) {
    v = fmaxf(v, __shfl_xor_sync(0xffffffffu, v, 16));
    v = fmaxf(v, __shfl_xor_sync(0xffffffffu, v, 8));
    v = fmaxf(v, __shfl_xor_sync(0xffffffffu, v, 4));
    v = fmaxf(v, __shfl_xor_sync(0xffffffffu, v, 2));
    v = fmaxf(v, __shfl_xor_sync(0xffffffffu, v, 1));
    return v;
}
__device__ __forceinline__ float blockAllReduceSum(float v, float* sh) {
    int lane = threadIdx.x & 31, wid = threadIdx.x >> 5;
    v = warpReduceSum(v);
    if (lane == 0) sh[wid] = v;
    __syncthreads();
    int nw = blockDim.x >> 5;
    float t = (lane < nw) ? sh[lane] : 0.0f;
    t = warpReduceSum(t);
    __syncthreads();
    return t;
}
__device__ __forceinline__ float blockAllReduceMax(float v, float* sh) {
    int lane = threadIdx.x & 31, wid = threadIdx.x >> 5;
    v = warpReduceMax(v);
    if (lane == 0) sh[wid] = v;
    __syncthreads();
    int nw = blockDim.x >> 5;
    float t = (lane < nw) ? sh[lane] : -3.0e38f;
    t = warpReduceMax(t);
    __syncthreads();
    return t;
}

// ======================================================================
// TF32 tensor-core GEMM, 128x128x32 tile, 256 threads (8 warps, 64x32 warp tile).
// BT=0: C = A[M,K] * B[K,N] (both row-major).
// BT=1: C = A[M,K] * Bt[N,K]^T (Bt row-major; NT gemm).
// EPI: 0 = none, 1 = dist (sqrt(max(rn[r]+cn[c]-2*acc,0))), 2 = relu.
// DUAL: A logical K = 2*512; first 512 from gA, rest from gA2 (both lda=512).
// M = gridDim.y*128, all dims multiples of tile sizes (no bounds checks).
// ======================================================================
template<int BT, int EPI, int DUAL>
__global__ __launch_bounds__(256)
void tc_gemm(const float* __restrict__ gA, const float* __restrict__ gA2,
             const float* __restrict__ gB, float* __restrict__ gC,
             int N, int K, int lda, int ldb,
             long long sA, long long sB, long long sC,
             const float* __restrict__ rn, const float* __restrict__ cn)
{
    __shared__ float As[128 * 36];   // [row][k] pad 36
    __shared__ float Bs[128 * 36];   // BT=0: [k][n] pad 136 (uses 32*136); BT=1: [n][k] pad 36

    const int tid  = threadIdx.x;
    const int wid  = tid >> 5, lane = tid & 31;
    const int gid  = lane >> 2, ctig = lane & 3;
    const int wm   = (wid & 1) * 64;
    const int wn   = (wid >> 1) * 32;

    const long long z = blockIdx.z;
    const float* Abase  = gA + z * sA + (long long)blockIdx.y * 128 * lda;
    const float* A2base = DUAL ? (gA2 + (long long)blockIdx.y * 128 * lda) : nullptr;
    const float* Bbase  = BT ? (gB + z * sB + (long long)blockIdx.x * 128 * ldb)
                             : (gB + z * sB + blockIdx.x * 128);
    float* Cbase = gC + z * sC + (long long)blockIdx.y * 128 * N + blockIdx.x * 128;

    // loader indices
    const int aRow = tid >> 1;            // 0..127
    const int aCol = (tid & 1) * 16;      // 0 or 16
    const int bRow = tid >> 3;            // 0..31   (NN)
    const int bCol = (tid & 7) * 4;       // 0..28   (NN)

    float4 pa[4], pb[4];

    auto loadA = [&](int k0) {
        const float* Ap = DUAL ? (k0 < 512 ? Abase + k0 : A2base + (k0 - 512))
                               : (Abase + k0);
        const float* r = Ap + (long long)aRow * lda + aCol;
#pragma unroll
        for (int j = 0; j < 4; j++) pa[j] = *(const float4*)(r + 4 * j);
    };
    auto loadB = [&](int k0) {
        if (BT) {
            const float* r = Bbase + (long long)aRow * ldb + k0 + aCol;
#pragma unroll
            for (int j = 0; j < 4; j++) pb[j] = *(const float4*)(r + 4 * j);
        } else {
            const float* r = Bbase + (long long)(k0 + bRow) * ldb + bCol;
#pragma unroll
            for (int j = 0; j < 4; j++) pb[j] = *(const float4*)(r + 32 * j);
        }
    };
    auto storeAB = [&] {
#pragma unroll
        for (int j = 0; j < 4; j++) {
            float4 t;
            t.x = to_tf32(pa[j].x); t.y = to_tf32(pa[j].y);
            t.z = to_tf32(pa[j].z); t.w = to_tf32(pa[j].w);
            *(float4*)&As[aRow * 36 + aCol + 4 * j] = t;
        }
#pragma unroll
        for (int j = 0; j < 4; j++) {
            float4 t;
            t.x = to_tf32(pb[j].x); t.y = to_tf32(pb[j].y);
            t.z = to_tf32(pb[j].z); t.w = to_tf32(pb[j].w);
            if (BT) *(float4*)&Bs[aRow * 36 + aCol + 4 * j] = t;
            else    *(float4*)&Bs[bRow * 136 + bCol + 32 * j] = t;
        }
    };

    float c[4][4][4];
#pragma unroll
    for (int mi = 0; mi < 4; mi++)
#pragma unroll
        for (int ni = 0; ni < 4; ni++)
#pragma unroll
            for (int r = 0; r < 4; r++) c[mi][ni][r] = 0.0f;

    loadA(0); loadB(0);

    for (int k0 = 0; k0 < K; k0 += 32) {
        storeAB();
        __syncthreads();
        if (k0 + 32 < K) { loadA(k0 + 32); loadB(k0 + 32); }

#pragma unroll
        for (int ks = 0; ks < 4; ks++) {
            const int kb = ks * 8;
            unsigned a[4][4], b[4][2];
#pragma unroll
            for (int mi = 0; mi < 4; mi++) {
                int r0 = wm + mi * 16 + gid;
                a[mi][0] = __float_as_uint(As[r0 * 36 + kb + ctig]);
                a[mi][1] = __float_as_uint(As[(r0 + 8) * 36 + kb + ctig]);
                a[mi][2] = __float_as_uint(As[r0 * 36 + kb + ctig + 4]);
                a[mi][3] = __float_as_uint(As[(r0 + 8) * 36 + kb + ctig + 4]);
            }
#pragma unroll
            for (int ni = 0; ni < 4; ni++) {
                int cc = wn + ni * 8 + gid;
                if (BT) {
                    b[ni][0] = __float_as_uint(Bs[cc * 36 + kb + ctig]);
                    b[ni][1] = __float_as_uint(Bs[cc * 36 + kb + ctig + 4]);
                } else {
                    b[ni][0] = __float_as_uint(Bs[(kb + ctig) * 136 + cc]);
                    b[ni][1] = __float_as_uint(Bs[(kb + ctig + 4) * 136 + cc]);
                }
            }
#pragma unroll
            for (int mi = 0; mi < 4; mi++)
#pragma unroll
                for (int ni = 0; ni < 4; ni++) {
                    asm volatile(
                        "mma.sync.aligned.m16n8k8.row.col.f32.tf32.tf32.f32 "
                        "{%0,%1,%2,%3}, {%4,%5,%6,%7}, {%8,%9}, {%0,%1,%2,%3};\n"
                        : "+f"(c[mi][ni][0]), "+f"(c[mi][ni][1]),
                          "+f"(c[mi][ni][2]), "+f"(c[mi][ni][3])
                        : "r"(a[mi][0]), "r"(a[mi][1]), "r"(a[mi][2]), "r"(a[mi][3]),
                          "r"(b[ni][0]), "r"(b[ni][1]));
                }
        }
        __syncthreads();
    }

    // epilogue
    const int Mloc = gridDim.y * 128;
    const float* rnp = (EPI == 1) ? (rn + z * Mloc + (long long)blockIdx.y * 128) : nullptr;
    const float* cnp = (EPI == 1) ? (cn + z * N + blockIdx.x * 128) : nullptr;

#pragma unroll
    for (int mi = 0; mi < 4; mi++) {
#pragma unroll
        for (int half = 0; half < 2; half++) {
            int r = wm + mi * 16 + gid + half * 8;
            float rv = (EPI == 1) ? rnp[r] : 0.0f;
#pragma unroll
            for (int ni = 0; ni < 4; ni++) {
                int cc = wn + ni * 8 + 2 * ctig;
                float v0 = c[mi][ni][half * 2 + 0];
                float v1 = c[mi][ni][half * 2 + 1];
                if (EPI == 1) {
                    v0 = sqrtf(fmaxf(rv + cnp[cc]     - 2.0f * v0, 0.0f));
                    v1 = sqrtf(fmaxf(rv + cnp[cc + 1] - 2.0f * v1, 0.0f));
                } else if (EPI == 2) {
                    v0 = fmaxf(v0, 0.0f);
                    v1 = fmaxf(v1, 0.0f);
                }
                *(float2*)(Cbase + (long long)r * N + cc) = make_float2(v0, v1);
            }
        }
    }
}

// ---------------- row squared-norm: out[row] = sum(X[row,:]^2), D = 512 ----------------
__global__ __launch_bounds__(128)
void rownorm2_kernel(const float* __restrict__ X, float* __restrict__ out)
{
    __shared__ float sh[32];
    long long row = blockIdx.x;
    const float* x = X + row * DD;
    float4 v = *(const float4*)(x + threadIdx.x * 4);
    float s = v.x * v.x + v.y * v.y + v.z * v.z + v.w * v.w;
    s = blockAllReduceSum(s, sh);
    if (threadIdx.x == 0) out[row] = s;
}

// ---------------- softmax over S=4096, in place on g_s ----------------
__global__ __launch_bounds__(256)
void softmax_rows_kernel()
{
    __shared__ float sh[32];
    long long row = blockIdx.x;           // NB*LQ rows
    float* p = g_s + row * SSEQ;
    int t = threadIdx.x;

    float4 f[4];
    float mx = -3.0e38f;
#pragma unroll
    for (int i = 0; i < 4; i++) {
        f[i] = *(const float4*)(p + i * 1024 + t * 4);
        mx = fmaxf(mx, fmaxf(fmaxf(f[i].x, f[i].y), fmaxf(f[i].z, f[i].w)));
    }
    mx = blockAllReduceMax(mx, sh);

    float sum = 0.0f;
#pragma unroll
    for (int i = 0; i < 4; i++) {
        f[i].x = __expf(f[i].x - mx);
        f[i].y = __expf(f[i].y - mx);
        f[i].z = __expf(f[i].z - mx);
        f[i].w = __expf(f[i].w - mx);
        sum += f[i].x + f[i].y + f[i].z + f[i].w;
    }
    sum = blockAllReduceSum(sum, sh);
    float r = 1.0f / sum;
#pragma unroll
    for (int i = 0; i < 4; i++) {
        f[i].x *= r; f[i].y *= r; f[i].z *= r; f[i].w *= r;
        *(float4*)(p + i * 1024 + t * 4) = f[i];
    }
}

// ---------------- LayerNorm over D=512 (+ optional residual) ----------------
__global__ __launch_bounds__(128)
void layernorm_kernel(const float* __restrict__ X, const float* __restrict__ G,
                      const float* __restrict__ Bv, const float* __restrict__ R,
                      float* __restrict__ O)
{
    __shared__ float sh[32];
    long long row = blockIdx.x;
    int c = threadIdx.x * 4;
    float4 v = *(const float4*)(X + row * DD + c);

    float s = v.x + v.y + v.z + v.w;
    s = blockAllReduceSum(s, sh);
    float mu = s * (1.0f / DD);

    float d0 = v.x - mu, d1 = v.y - mu, d2 = v.z - mu, d3 = v.w - mu;
    float s2 = d0 * d0 + d1 * d1 + d2 * d2 + d3 * d3;
    s2 = blockAllReduceSum(s2, sh);
    float inv = rsqrtf(s2 * (1.0f / DD) + 1e-5f);

    float4 gg = *(const float4*)(G + c);
    float4 bb = *(const float4*)(Bv + c);
    float4 o;
    o.x = d0 * inv * gg.x + bb.x;
    o.y = d1 * inv * gg.y + bb.y;
    o.z = d2 * inv * gg.z + bb.z;
    o.w = d3 * inv * gg.w + bb.w;
    if (R) {
        float4 rr = *(const float4*)(R + row * DD + c);
        o.x += rr.x; o.y += rr.y; o.z += rr.z; o.w += rr.w;
    }
    *(float4*)(O + row * DD + c) = o;
}

// ======================================================================
extern "C" void kernel_launch(void* const* d_in, const int* in_sizes, int n_in,
                              void* d_out, int out_size)
{
    (void)in_sizes; (void)n_in; (void)out_size;
    const float* x   = (const float*)d_in[0];
    const float* src = (const float*)d_in[1];
    const float* Wq  = (const float*)d_in[2];
    const float* Wk  = (const float*)d_in[3];
    const float* Wv  = (const float*)d_in[4];
    const float* Wm  = (const float*)d_in[5];
    const float* W1  = (const float*)d_in[6];
    const float* W2  = (const float*)d_in[7];
    const float* g1  = (const float*)d_in[8];
    const float* b1  = (const float*)d_in[9];
    const float* g2  = (const float*)d_in[10];
    const float* b2  = (const float*)d_in[11];
    float* out = (float*)d_out;

    float *q, *k, *v, *q2, *k2, *sc, *msg, *mw, *mln, *hid, *ffn;
    cudaGetSymbolAddress((void**)&q,   g_q);
    cudaGetSymbolAddress((void**)&k,   g_k);
    cudaGetSymbolAddress((void**)&v,   g_v);
    cudaGetSymbolAddress((void**)&q2,  g_q2);
    cudaGetSymbolAddress((void**)&k2,  g_k2);
    cudaGetSymbolAddress((void**)&sc,  g_s);
    cudaGetSymbolAddress((void**)&msg, g_msg);
    cudaGetSymbolAddress((void**)&mw,  g_mw);
    cudaGetSymbolAddress((void**)&mln, g_mln);
    cudaGetSymbolAddress((void**)&hid, g_hid);
    cudaGetSymbolAddress((void**)&ffn, g_ffn);

    // 1. projections (tf32 tensor cores)
    tc_gemm<0,0,0><<<dim3(4, 64, 1),  256>>>(x,   nullptr, Wq, q, DD, DD, DD, DD, 0, 0, 0, nullptr, nullptr);
    tc_gemm<0,0,0><<<dim3(4, 256, 1), 256>>>(src, nullptr, Wk, k, DD, DD, DD, DD, 0, 0, 0, nullptr, nullptr);
    tc_gemm<0,0,0><<<dim3(4, 256, 1), 256>>>(src, nullptr, Wv, v, DD, DD, DD, DD, 0, 0, 0, nullptr, nullptr);

    // 2. squared row norms
    rownorm2_kernel<<<NB * LQ,   128>>>(q, q2);
    rownorm2_kernel<<<NB * SSEQ, 128>>>(k, k2);

    // 3. pairwise distances: sc = sqrt(max(q2 + k2 - 2 q.k, 0))   [batched NT, fused epi]
    tc_gemm<1,1,0><<<dim3(SSEQ / 128, LQ / 128, NB), 256>>>(
        q, nullptr, k, sc, SSEQ, DD, DD, DD,
        (long long)LQ * DD, (long long)SSEQ * DD, (long long)LQ * SSEQ, q2, k2);

    // 4. softmax over S (in place)
    softmax_rows_kernel<<<NB * LQ, 256>>>();

    // 5. message = attn @ v   [batched NN]
    tc_gemm<0,0,0><<<dim3(4, LQ / 128, NB), 256>>>(
        sc, nullptr, v, msg, DD, SSEQ, SSEQ, DD,
        (long long)LQ * SSEQ, (long long)SSEQ * DD, (long long)LQ * DD, nullptr, nullptr);

    // 6. mw = message @ Wm ; mln = LN(mw, g1, b1)
    tc_gemm<0,0,0><<<dim3(4, 64, 1), 256>>>(msg, nullptr, Wm, mw, DD, DD, DD, DD, 0, 0, 0, nullptr, nullptr);
    layernorm_kernel<<<NB * LQ, 128>>>(mw, g1, b1, nullptr, mln);

    // 7. hid = relu([x, mln] @ W1)   [dual-A, fused relu]
    tc_gemm<0,2,1><<<dim3(8, 64, 1), 256>>>(x, mln, W1, hid, 2 * DD, 2 * DD, DD, 2 * DD, 0, 0, 0, nullptr, nullptr);

    // 8. ffn = hid @ W2
    tc_gemm<0,0,0><<<dim3(4, 64, 1), 256>>>(hid, nullptr, W2, ffn, DD, 2 * DD, 2 * DD, DD, 0, 0, 0, nullptr, nullptr);

    // 9. out = x + LN(ffn, g2, b2)
    layernorm_kernel<<<NB * LQ, 128>>>(ffn, g2, b2, x, out);
}